// round 3
// baseline (speedup 1.0000x reference)
#include <cuda_runtime.h>
#include <cooperative_groups.h>
#include <cstdint>

namespace cgx = cooperative_groups;

// Problem constants
constexpr int B_  = 256;
constexpr int T_  = 512;
constexpr int H_  = 256;
constexpr int MTOT = B_ * T_;              // 131072 rows for projection GEMM
constexpr size_t MH = (size_t)MTOT * H_;   // elements per gate in g_xp

// Scan decomposition: 16 batch groups x 8 column CTAs (one cluster per group)
constexpr int NC  = 8;    // column groups per cluster (32 cols each)
constexpr int HC  = 32;
constexpr int NBG = 16;   // batch groups
constexpr int NB  = 16;   // batch rows per group

// ---------------- device scratch ----------------
__device__ float g_xp[3 * MH];     // projected inputs [gate][m][H] (~403MB)

// ---------------- f32x2 helpers ----------------
__device__ __forceinline__ unsigned long long pack2(float a, float b) {
    unsigned long long r;
    asm("mov.b64 %0, {%1,%2};" : "=l"(r) : "f"(a), "f"(b));
    return r;
}
__device__ __forceinline__ void fma2(unsigned long long& d, unsigned long long a, unsigned long long b) {
    asm("fma.rn.f32x2 %0, %1, %2, %0;" : "+l"(d) : "l"(a), "l"(b));
}
__device__ __forceinline__ float fold2(unsigned long long v) {
    float lo, hi;
    asm("mov.b64 {%0,%1}, %2;" : "=f"(lo), "=f"(hi) : "l"(v));
    return lo + hi;
}
__device__ __forceinline__ void unpack2(unsigned long long v, float& lo, float& hi) {
    asm("mov.b64 {%0,%1}, %2;" : "=f"(lo), "=f"(hi) : "l"(v));
}

__device__ __forceinline__ float sigmoid_(float v) {
    float e = __expf(-v);
    return __fdividef(1.f, 1.f + e);
}
__device__ __forceinline__ float tanh_(float v) {
    float e = __expf(2.f * v);
    return __fdividef(e - 1.f, e + 1.f);
}

// ================= projection GEMM (all 3 gates fused, f32x2) =================
// g_xp[g] = x @ W_g + b_g.  x:[131072,128], W:[128,256]. Tile 128M x 64N, BK=32.
__global__ __launch_bounds__(256) void proj_kernel(
    const float* __restrict__ x,
    const float* __restrict__ Wz, const float* __restrict__ Wr, const float* __restrict__ Wh,
    const float* __restrict__ bz, const float* __restrict__ br, const float* __restrict__ bh)
{
    __shared__ float As[32 * 132];    // [k][m] transposed, pad 132   (16.9KB)
    __shared__ float Bs[3][32 * 64];  // [g][k][n]                    (24KB)

    const int mtile = blockIdx.x * 128;
    const int ntile = blockIdx.y * 64;
    const int tid = threadIdx.x;
    const int tm = tid >> 4;      // 0..15 -> 8 m-rows each
    const int tn = tid & 15;      // 0..15 -> 4 n-cols each

    // accumulators: per gate, per m-row, two f32x2 lanes covering 4 n-cols
    unsigned long long acc[3][8][2] = {};

    for (int kc = 0; kc < 128; kc += 32) {
        __syncthreads();
        // stage A chunk [128m x 32k] -> As[k][m]
        #pragma unroll
        for (int it = 0; it < 4; ++it) {
            int idx = tid + it * 256;
            int m = idx >> 3, c4 = idx & 7;
            float4 v = *(const float4*)&x[(size_t)(mtile + m) * 128 + kc + c4 * 4];
            As[(c4 * 4 + 0) * 132 + m] = v.x;
            As[(c4 * 4 + 1) * 132 + m] = v.y;
            As[(c4 * 4 + 2) * 132 + m] = v.z;
            As[(c4 * 4 + 3) * 132 + m] = v.w;
        }
        // stage B chunks for all 3 gates
        #pragma unroll
        for (int it = 0; it < 2; ++it) {
            int idx = tid + it * 256;
            int kk = idx >> 4, n4 = idx & 15;
            size_t off = (size_t)(kc + kk) * 256 + ntile + n4 * 4;
            *(float4*)&Bs[0][kk * 64 + n4 * 4] = *(const float4*)&Wz[off];
            *(float4*)&Bs[1][kk * 64 + n4 * 4] = *(const float4*)&Wr[off];
            *(float4*)&Bs[2][kk * 64 + n4 * 4] = *(const float4*)&Wh[off];
        }
        __syncthreads();

        #pragma unroll
        for (int kk = 0; kk < 32; ++kk) {
            float4 a0 = *(const float4*)&As[kk * 132 + tm * 8];
            float4 a1 = *(const float4*)&As[kk * 132 + tm * 8 + 4];
            float a[8] = {a0.x, a0.y, a0.z, a0.w, a1.x, a1.y, a1.z, a1.w};
            unsigned long long b2[3][2];
            #pragma unroll
            for (int g = 0; g < 3; ++g) {
                float4 bv = *(const float4*)&Bs[g][kk * 64 + tn * 4];
                b2[g][0] = pack2(bv.x, bv.y);
                b2[g][1] = pack2(bv.z, bv.w);
            }
            #pragma unroll
            for (int i = 0; i < 8; ++i) {
                unsigned long long a2 = pack2(a[i], a[i]);
                #pragma unroll
                for (int g = 0; g < 3; ++g) {
                    fma2(acc[g][i][0], a2, b2[g][0]);
                    fma2(acc[g][i][1], a2, b2[g][1]);
                }
            }
        }
    }

    float4 bias4[3];
    bias4[0] = *(const float4*)&bz[ntile + tn * 4];
    bias4[1] = *(const float4*)&br[ntile + tn * 4];
    bias4[2] = *(const float4*)&bh[ntile + tn * 4];

    #pragma unroll
    for (int g = 0; g < 3; ++g) {
        float* out = g_xp + (size_t)g * MH;
        #pragma unroll
        for (int i = 0; i < 8; ++i) {
            float o0, o1, o2, o3;
            unpack2(acc[g][i][0], o0, o1);
            unpack2(acc[g][i][1], o2, o3);
            float4 o = make_float4(o0 + bias4[g].x, o1 + bias4[g].y,
                                   o2 + bias4[g].z, o3 + bias4[g].w);
            *(float4*)&out[(size_t)(mtile + tm * 8 + i) * 256 + ntile + tn * 4] = o;
        }
    }
}

// ================= persistent recurrent scan (clusters of 8 CTAs) =================
// CTA = (batch group grp = blockIdx.x/8, column group = cluster rank).
// Each CTA holds U[:, rank*32 : rank*32+32] for all 3 gates in registers
// (k split across 8 warps). h/rh slices exchanged via DSMEM + barrier.cluster.
__global__ void __cluster_dims__(NC, 1, 1) __launch_bounds__(256, 1)
scan_kernel(
    const float* __restrict__ Uz, const float* __restrict__ Ur, const float* __restrict__ Uh,
    const float* __restrict__ hdecay, float* __restrict__ out)
{
    extern __shared__ float sm[];
    float* asm_s  = sm;              // [16][256] assembled hdec / rh   (16KB)
    float* red_z  = sm + 4096;       // [8][16][32]                     (16KB)
    float* red_r  = sm + 8192;       // [8][16][32]                     (16KB)
    float* h_loc  = sm + 12288;      // [16][32] own h slice            (2KB)
    float* rh_loc = sm + 12800;      // [16][32] own rh slice           (2KB)

    const int tid = threadIdx.x;
    const int w = tid >> 5;          // warp -> k block [32w, 32w+32)
    const int l = tid & 31;          // lane -> local column
    const int grp = blockIdx.x >> 3;

    cgx::cluster_group cl = cgx::this_cluster();
    const int rank = cl.block_rank();
    const int j = rank * HC + l;     // global column this thread owns
    const int b0g = grp * NB;        // global batch base

    // --- load weight slices into registers as packed f32x2 over k-pairs ---
    unsigned long long uz2[16], ur2[16], uh2[16];
    #pragma unroll
    for (int p = 0; p < 16; ++p) {
        int k = w * 32 + 2 * p;
        uz2[p] = pack2(Uz[(size_t)k * H_ + j], Uz[(size_t)(k + 1) * H_ + j]);
        ur2[p] = pack2(Ur[(size_t)k * H_ + j], Ur[(size_t)(k + 1) * H_ + j]);
        uh2[p] = pack2(Uh[(size_t)k * H_ + j], Uh[(size_t)(k + 1) * H_ + j]);
    }

    // --- DSMEM assembly mapping: each thread reads from ONE fixed peer ---
    const int peer = (tid & 63) >> 3;   // source CTA rank for this thread
    const int c8   = tid & 7;           // float4 slot within peer's 32-col slice
    const int brow = tid >> 6;          // base batch row (0..3); rows brow+4*it
    const float4* peer_h  = (const float4*)cl.map_shared_rank((void*)h_loc,  peer);
    const float4* peer_rh = (const float4*)cl.map_shared_rank((void*)rh_loc, peer);

    for (int t = 0; t < T_; ++t) {
        // This thread finalizes rows (b=w, j) and (b=w+8, j).
        const size_t m0 = (size_t)(b0g + w) * T_ + t;
        const size_t m1 = (size_t)(b0g + w + 8) * T_ + t;
        // prefetch projected inputs (streaming HBM) early
        float xz0 = g_xp[m0 * 256 + j],          xz1 = g_xp[m1 * 256 + j];
        float xr0 = g_xp[MH + m0 * 256 + j],     xr1 = g_xp[MH + m1 * 256 + j];
        float xh0 = g_xp[2 * MH + m0 * 256 + j], xh1 = g_xp[2 * MH + m1 * 256 + j];

        // ---- phase 0: assemble hdec = dec_t * h_{t-1} from cluster peers ----
        if (t == 0) {
            #pragma unroll
            for (int i = 0; i < 16; ++i) asm_s[tid + i * 256] = 0.f;
        } else {
            // warp-local decay values: rows covered by this warp are brow+4*it
            float dec_l = 0.f;
            if (l < 4) dec_l = hdecay[(size_t)(b0g + brow + 4 * l) * T_ + t];
            #pragma unroll
            for (int it = 0; it < 4; ++it) {
                int b = brow + 4 * it;
                float dec = __shfl_sync(0xffffffffu, dec_l, it);
                float4 v = peer_h[b * 8 + c8];
                float4 o = make_float4(v.x * dec, v.y * dec, v.z * dec, v.w * dec);
                *(float4*)&asm_s[b * 256 + peer * 32 + c8 * 4] = o;
            }
        }
        __syncthreads();

        // ---- phase 1: z,r partial dot products (weights in regs, f32x2) ----
        #pragma unroll 1
        for (int b = 0; b < NB; ++b) {
            unsigned long long az0 = 0, az1 = 0, ar0 = 0, ar1 = 0;
            const float* hrow = &asm_s[b * 256 + w * 32];
            #pragma unroll
            for (int q = 0; q < 8; ++q) {
                ulonglong2 hv = *(const ulonglong2*)(hrow + q * 4);
                fma2(az0, hv.x, uz2[2 * q]);
                fma2(az1, hv.y, uz2[2 * q + 1]);
                fma2(ar0, hv.x, ur2[2 * q]);
                fma2(ar1, hv.y, ur2[2 * q + 1]);
            }
            red_z[(w * 16 + b) * 32 + l] = fold2(az0) + fold2(az1);
            red_r[(w * 16 + b) * 32 + l] = fold2(ar0) + fold2(ar1);
        }
        __syncthreads();

        // ---- phase 2: reduce across warps, activations, publish rh slice ----
        float zv0, zv1, hd0, hd1;
        {
            float sz0 = 0, sr0 = 0, sz1 = 0, sr1 = 0;
            #pragma unroll
            for (int ww = 0; ww < 8; ++ww) {
                sz0 += red_z[(ww * 16 + w) * 32 + l];
                sr0 += red_r[(ww * 16 + w) * 32 + l];
                sz1 += red_z[(ww * 16 + w + 8) * 32 + l];
                sr1 += red_r[(ww * 16 + w + 8) * 32 + l];
            }
            sz0 += xz0; sz1 += xz1; sr0 += xr0; sr1 += xr1;
            zv0 = sigmoid_(sz0); zv1 = sigmoid_(sz1);
            float r0 = sigmoid_(sr0), r1 = sigmoid_(sr1);
            hd0 = asm_s[w * 256 + j];
            hd1 = asm_s[(w + 8) * 256 + j];
            rh_loc[w * 32 + l]       = r0 * hd0;
            rh_loc[(w + 8) * 32 + l] = r1 * hd1;
        }
        cl.sync();   // rh slices visible cluster-wide (release/acquire)

        // ---- phase 3: assemble full rh rows from peers (hd kept in regs) ----
        #pragma unroll
        for (int it = 0; it < 4; ++it) {
            int b = brow + 4 * it;
            float4 v = peer_rh[b * 8 + c8];
            *(float4*)&asm_s[b * 256 + peer * 32 + c8 * 4] = v;
        }
        __syncthreads();

        // ---- phase 4: h_prop partial dot products ----
        #pragma unroll 1
        for (int b = 0; b < NB; ++b) {
            unsigned long long ah0 = 0, ah1 = 0;
            const float* hrow = &asm_s[b * 256 + w * 32];
            #pragma unroll
            for (int q = 0; q < 8; ++q) {
                ulonglong2 hv = *(const ulonglong2*)(hrow + q * 4);
                fma2(ah0, hv.x, uh2[2 * q]);
                fma2(ah1, hv.y, uh2[2 * q + 1]);
            }
            red_z[(w * 16 + b) * 32 + l] = fold2(ah0) + fold2(ah1);
        }
        __syncthreads();

        // ---- phase 5: reduce, combine, publish h + write output ----
        {
            float sh0 = 0, sh1 = 0;
            #pragma unroll
            for (int ww = 0; ww < 8; ++ww) {
                sh0 += red_z[(ww * 16 + w) * 32 + l];
                sh1 += red_z[(ww * 16 + w + 8) * 32 + l];
            }
            sh0 += xh0; sh1 += xh1;
            float hp0 = tanh_(sh0), hp1 = tanh_(sh1);
            float h0 = (1.f - zv0) * hd0 + zv0 * hp0;
            float h1 = (1.f - zv1) * hd1 + zv1 * hp1;
            h_loc[w * 32 + l]       = h0;
            h_loc[(w + 8) * 32 + l] = h1;
            out[m0 * 256 + j] = h0;
            out[m1 * 256 + j] = h1;
        }
        cl.sync();   // h slices visible cluster-wide
    }
}

// ================= launch =================
extern "C" void kernel_launch(void* const* d_in, const int* /*in_sizes*/, int /*n_in*/,
                              void* d_out, int /*out_size*/)
{
    const float* x      = (const float*)d_in[0];
    const float* hdecay = (const float*)d_in[1];
    const float* Wr = (const float*)d_in[2];
    const float* Wz = (const float*)d_in[3];
    const float* Wh = (const float*)d_in[4];
    const float* Ur = (const float*)d_in[5];
    const float* Uz = (const float*)d_in[6];
    const float* Uh = (const float*)d_in[7];
    const float* br = (const float*)d_in[8];
    const float* bz = (const float*)d_in[9];
    const float* bh = (const float*)d_in[10];
    float* out = (float*)d_out;

    // gate order in g_xp: 0 = z, 1 = r, 2 = h
    proj_kernel<<<dim3(MTOT / 128, H_ / 64), 256>>>(x, Wz, Wr, Wh, bz, br, bh);

    constexpr int SMEM_SCAN = 13312 * 4;   // 52KB dynamic
    static bool attr_set = false;
    if (!attr_set) {
        cudaFuncSetAttribute(scan_kernel, cudaFuncAttributeMaxDynamicSharedMemorySize, SMEM_SCAN);
        attr_set = true;
    }
    scan_kernel<<<NBG * NC, 256, SMEM_SCAN>>>(Uz, Ur, Uh, hdecay, out);
}

// round 4
// speedup vs baseline: 1.5900x; 1.5900x over previous
#include <cuda_runtime.h>
#include <cstdint>

// Problem constants
constexpr int B_  = 256;
constexpr int T_  = 512;
constexpr int H_  = 256;
constexpr int MTOT = B_ * T_;              // 131072 rows for projection GEMM
constexpr size_t MH = (size_t)MTOT * H_;   // elements per gate in g_xp

// Scan decomposition
constexpr int NC  = 8;    // column groups (each owns 32 columns of U)
constexpr int HC  = 32;
constexpr int NBG = 16;   // batch groups
constexpr int NB  = 16;   // batch rows per group

// ---------------- device scratch ----------------
__device__ float g_xp[3 * MH];               // projected inputs [gate][m][H]
__device__ float g_h [NBG][NB][H_];          // pre-decayed h exchange
__device__ float g_rh[NBG][NB][H_];          // (r * h_dec) exchange
__device__ unsigned int g_ctr[NBG][2];       // per-group barrier counters

// ---------------- f32x2 helpers ----------------
__device__ __forceinline__ unsigned long long pack2(float a, float b) {
    unsigned long long r;
    asm("mov.b64 %0, {%1,%2};" : "=l"(r) : "f"(a), "f"(b));
    return r;
}
__device__ __forceinline__ void fma2(unsigned long long& d, unsigned long long a, unsigned long long b) {
    asm("fma.rn.f32x2 %0, %1, %2, %0;" : "+l"(d) : "l"(a), "l"(b));
}
__device__ __forceinline__ float fold2(unsigned long long v) {
    float lo, hi;
    asm("mov.b64 {%0,%1}, %2;" : "=f"(lo), "=f"(hi) : "l"(v));
    return lo + hi;
}

__device__ __forceinline__ float sigmoid_(float v) {
    float e = __expf(-v);
    return __fdividef(1.f, 1.f + e);
}
__device__ __forceinline__ float tanh_(float v) {
    float e = __expf(2.f * v);
    return __fdividef(e - 1.f, e + 1.f);
}

// ---------------- inter-CTA barrier primitives ----------------
__device__ __forceinline__ void bar_arrive(unsigned* c) {
    asm volatile("red.release.gpu.global.add.u32 [%0], %1;" :: "l"(c), "r"(1u) : "memory");
}
__device__ __forceinline__ void bar_wait(unsigned* c, unsigned tgt) {
    unsigned v;
    do {
        asm volatile("ld.acquire.gpu.global.u32 %0, [%1];" : "=r"(v) : "l"(c) : "memory");
    } while (v < tgt);
}

// ================= projection GEMM (R2 version, measured 570us) =================
__global__ __launch_bounds__(256) void proj_kernel(
    const float* __restrict__ x,
    const float* __restrict__ Wz, const float* __restrict__ Wr, const float* __restrict__ Wh,
    const float* __restrict__ bz, const float* __restrict__ br, const float* __restrict__ bh)
{
    __shared__ float As[32 * 132];
    __shared__ float Bs[32 * 64];

    const int g = blockIdx.z;
    const float* W    = (g == 0) ? Wz : (g == 1) ? Wr : Wh;
    const float* bias = (g == 0) ? bz : (g == 1) ? br : bh;
    float* out = g_xp + (size_t)g * MH;

    const int mtile = blockIdx.x * 128;
    const int ntile = blockIdx.y * 64;
    const int tid = threadIdx.x;
    const int tm = tid >> 4;
    const int tn = tid & 15;

    float acc[8][4] = {};

    for (int kc = 0; kc < 128; kc += 32) {
        __syncthreads();
        #pragma unroll
        for (int it = 0; it < 4; ++it) {
            int idx = tid + it * 256;
            int m = idx >> 3, c4 = idx & 7;
            float4 v = *(const float4*)&x[(size_t)(mtile + m) * 128 + kc + c4 * 4];
            As[(c4 * 4 + 0) * 132 + m] = v.x;
            As[(c4 * 4 + 1) * 132 + m] = v.y;
            As[(c4 * 4 + 2) * 132 + m] = v.z;
            As[(c4 * 4 + 3) * 132 + m] = v.w;
        }
        #pragma unroll
        for (int it = 0; it < 2; ++it) {
            int idx = tid + it * 256;
            int kk = idx >> 4, n4 = idx & 15;
            float4 v = *(const float4*)&W[(size_t)(kc + kk) * 256 + ntile + n4 * 4];
            *(float4*)&Bs[kk * 64 + n4 * 4] = v;
        }
        __syncthreads();

        #pragma unroll
        for (int kk = 0; kk < 32; ++kk) {
            float4 a0 = *(const float4*)&As[kk * 132 + tm * 8];
            float4 a1 = *(const float4*)&As[kk * 132 + tm * 8 + 4];
            float4 bv = *(const float4*)&Bs[kk * 64 + tn * 4];
            float a[8] = {a0.x, a0.y, a0.z, a0.w, a1.x, a1.y, a1.z, a1.w};
            #pragma unroll
            for (int i = 0; i < 8; i++) {
                acc[i][0] += a[i] * bv.x;
                acc[i][1] += a[i] * bv.y;
                acc[i][2] += a[i] * bv.z;
                acc[i][3] += a[i] * bv.w;
            }
        }
    }

    float4 bb = *(const float4*)&bias[ntile + tn * 4];
    #pragma unroll
    for (int i = 0; i < 8; i++) {
        float4 o = make_float4(acc[i][0] + bb.x, acc[i][1] + bb.y,
                               acc[i][2] + bb.z, acc[i][3] + bb.w);
        *(float4*)&out[(size_t)(mtile + tm * 8 + i) * 256 + ntile + tn * 4] = o;
    }
}

// ================= barrier reset =================
__global__ void reset_kernel() {
    if (threadIdx.x < NBG * 2) ((unsigned*)g_ctr)[threadIdx.x] = 0;
}

// ================= persistent recurrent scan =================
// CTA = (batch group grp, column group cg). Weights U[:, cg*32..+32) for all
// 3 gates live in registers (k split across 8 warps).
// Barrier A (rh ready) is hidden behind the z-GEMM; publishes carry
// next-step decay so consumers do a straight copy.
__global__ __launch_bounds__(256, 1) void scan_kernel(
    const float* __restrict__ Uz, const float* __restrict__ Ur, const float* __restrict__ Uh,
    const float* __restrict__ hdecay, float* __restrict__ out)
{
    extern __shared__ float sm[];
    float* asm_s  = sm;              // [16][256] assembled hdec / rh
    float* red_z  = sm + 4096;       // [8][16][32]
    float* red_r  = sm + 8192;       // [8][16][32]

    const int tid = threadIdx.x;
    const int w = tid >> 5;          // warp -> k block [32w, 32w+32)
    const int l = tid & 31;          // lane -> local column
    const int grp = blockIdx.x >> 3;
    const int cg  = blockIdx.x & 7;
    const int j = cg * HC + l;       // global column
    const int b0g = grp * NB;

    // --- weight slices into registers as packed f32x2 over k-pairs ---
    unsigned long long uz2[16], ur2[16], uh2[16];
    #pragma unroll
    for (int p = 0; p < 16; ++p) {
        int k = w * 32 + 2 * p;
        uz2[p] = pack2(Uz[(size_t)k * H_ + j], Uz[(size_t)(k + 1) * H_ + j]);
        ur2[p] = pack2(Ur[(size_t)k * H_ + j], Ur[(size_t)(k + 1) * H_ + j]);
        uh2[p] = pack2(Uh[(size_t)k * H_ + j], Uh[(size_t)(k + 1) * H_ + j]);
    }

    unsigned* ctrA = &g_ctr[grp][0];
    unsigned* ctrB = &g_ctr[grp][1];

    // h_dec(t=0) = 0
    #pragma unroll
    for (int i = 0; i < 16; ++i) asm_s[tid + i * 256] = 0.f;
    __syncthreads();

    for (int t = 0; t < T_; ++t) {
        const unsigned tgt = (unsigned)(t + 1) * NC;
        const size_t m0 = (size_t)(b0g + w) * T_ + t;
        const size_t m1 = (size_t)(b0g + w + 8) * T_ + t;

        // prefetch projected inputs + next-step decay (warp-uniform broadcast)
        float xz0 = g_xp[m0 * 256 + j],          xz1 = g_xp[m1 * 256 + j];
        float xr0 = g_xp[MH + m0 * 256 + j],     xr1 = g_xp[MH + m1 * 256 + j];
        float xh0 = g_xp[2 * MH + m0 * 256 + j], xh1 = g_xp[2 * MH + m1 * 256 + j];
        float decn0 = 0.f, decn1 = 0.f;
        if (t + 1 < T_) {
            decn0 = hdecay[(size_t)(b0g + w) * T_ + t + 1];
            decn1 = hdecay[(size_t)(b0g + w + 8) * T_ + t + 1];
        }
        // own h_dec values (survive asm_s overwrite in phase 3)
        const float hd0 = asm_s[w * 256 + j];
        const float hd1 = asm_s[(w + 8) * 256 + j];

        // ---- phase 1r: r partial dot products only ----
        #pragma unroll 1
        for (int b = 0; b < NB; ++b) {
            unsigned long long ar0 = 0, ar1 = 0;
            const float* hrow = &asm_s[b * 256 + w * 32];
            #pragma unroll
            for (int q = 0; q < 8; ++q) {
                ulonglong2 hv = *(const ulonglong2*)(hrow + q * 4);
                fma2(ar0, hv.x, ur2[2 * q]);
                fma2(ar1, hv.y, ur2[2 * q + 1]);
            }
            red_r[(w * 16 + b) * 32 + l] = fold2(ar0) + fold2(ar1);
        }
        __syncthreads();

        // ---- r reduce + publish rh, arrive at barrier A ----
        {
            float sr0 = xr0, sr1 = xr1;
            #pragma unroll
            for (int ww = 0; ww < 8; ++ww) {
                sr0 += red_r[(ww * 16 + w) * 32 + l];
                sr1 += red_r[(ww * 16 + w + 8) * 32 + l];
            }
            float r0 = sigmoid_(sr0), r1 = sigmoid_(sr1);
            __stcg(&g_rh[grp][w][j],     r0 * hd0);
            __stcg(&g_rh[grp][w + 8][j], r1 * hd1);
        }
        __threadfence();      // make rh visible at gpu scope before arrival
        __syncthreads();      // all threads fenced before tid0 signals
        if (tid == 0) bar_arrive(ctrA);

        // ---- phase 1z: z GEMM (hides barrier-A propagation) ----
        #pragma unroll 1
        for (int b = 0; b < NB; ++b) {
            unsigned long long az0 = 0, az1 = 0;
            const float* hrow = &asm_s[b * 256 + w * 32];
            #pragma unroll
            for (int q = 0; q < 8; ++q) {
                ulonglong2 hv = *(const ulonglong2*)(hrow + q * 4);
                fma2(az0, hv.x, uz2[2 * q]);
                fma2(az1, hv.y, uz2[2 * q + 1]);
            }
            red_z[(w * 16 + b) * 32 + l] = fold2(az0) + fold2(az1);
        }
        __syncthreads();

        float zv0, zv1;
        {
            float sz0 = xz0, sz1 = xz1;
            #pragma unroll
            for (int ww = 0; ww < 8; ++ww) {
                sz0 += red_z[(ww * 16 + w) * 32 + l];
                sz1 += red_z[(ww * 16 + w + 8) * 32 + l];
            }
            zv0 = sigmoid_(sz0); zv1 = sigmoid_(sz1);
        }
        if (tid == 0) bar_wait(ctrA, tgt);
        __syncthreads();

        // ---- phase 3: pull full rh rows from L2 ----
        #pragma unroll
        for (int it = 0; it < 4; ++it) {
            int idx = tid + it * 256;
            int b = idx >> 6, k4 = idx & 63;
            float4 v = __ldcg((const float4*)&g_rh[grp][b][k4 * 4]);
            *(float4*)&asm_s[b * 256 + k4 * 4] = v;
        }
        __syncthreads();

        // ---- phase 4: h_prop partial dot products ----
        #pragma unroll 1
        for (int b = 0; b < NB; ++b) {
            unsigned long long ah0 = 0, ah1 = 0;
            const float* hrow = &asm_s[b * 256 + w * 32];
            #pragma unroll
            for (int q = 0; q < 8; ++q) {
                ulonglong2 hv = *(const ulonglong2*)(hrow + q * 4);
                fma2(ah0, hv.x, uh2[2 * q]);
                fma2(ah1, hv.y, uh2[2 * q + 1]);
            }
            red_z[(w * 16 + b) * 32 + l] = fold2(ah0) + fold2(ah1);
        }
        __syncthreads();

        // ---- phase 5: reduce, combine, publish pre-decayed h ----
        {
            float sh0 = xh0, sh1 = xh1;
            #pragma unroll
            for (int ww = 0; ww < 8; ++ww) {
                sh0 += red_z[(ww * 16 + w) * 32 + l];
                sh1 += red_z[(ww * 16 + w + 8) * 32 + l];
            }
            float hp0 = tanh_(sh0), hp1 = tanh_(sh1);
            float h0 = (1.f - zv0) * hd0 + zv0 * hp0;
            float h1 = (1.f - zv1) * hd1 + zv1 * hp1;
            __stcg(&out[m0 * 256 + j], h0);
            __stcg(&out[m1 * 256 + j], h1);
            __stcg(&g_h[grp][w][j],     h0 * decn0);   // next step's h_dec
            __stcg(&g_h[grp][w + 8][j], h1 * decn1);
        }
        __threadfence();
        __syncthreads();
        if (tid == 0) { bar_arrive(ctrB); bar_wait(ctrB, tgt); }
        __syncthreads();

        // ---- phase 0': assemble next h_dec (already decayed) ----
        if (t + 1 < T_) {
            #pragma unroll
            for (int it = 0; it < 4; ++it) {
                int idx = tid + it * 256;
                int b = idx >> 6, k4 = idx & 63;
                float4 v = __ldcg((const float4*)&g_h[grp][b][k4 * 4]);
                *(float4*)&asm_s[b * 256 + k4 * 4] = v;
            }
            __syncthreads();
        }
    }
}

// ================= launch =================
extern "C" void kernel_launch(void* const* d_in, const int* /*in_sizes*/, int /*n_in*/,
                              void* d_out, int /*out_size*/)
{
    const float* x      = (const float*)d_in[0];
    const float* hdecay = (const float*)d_in[1];
    const float* Wr = (const float*)d_in[2];
    const float* Wz = (const float*)d_in[3];
    const float* Wh = (const float*)d_in[4];
    const float* Ur = (const float*)d_in[5];
    const float* Uz = (const float*)d_in[6];
    const float* Uh = (const float*)d_in[7];
    const float* br = (const float*)d_in[8];
    const float* bz = (const float*)d_in[9];
    const float* bh = (const float*)d_in[10];
    float* out = (float*)d_out;

    proj_kernel<<<dim3(MTOT / 128, H_ / 64, 3), 256>>>(x, Wz, Wr, Wh, bz, br, bh);
    reset_kernel<<<1, 32>>>();
    scan_kernel<<<NBG * NC, 256, 49152>>>(Uz, Ur, Uh, hdecay, out);
}

// round 5
// speedup vs baseline: 1.6695x; 1.0499x over previous
#include <cuda_runtime.h>
#include <cstdint>

// Problem constants
constexpr int B_  = 256;
constexpr int T_  = 512;
constexpr int H_  = 256;
constexpr int MTOT = B_ * T_;
constexpr size_t MH = (size_t)MTOT * H_;

// Scan decomposition
constexpr int NC  = 8;    // column groups (32 cols each)
constexpr int HC  = 32;
constexpr int NBG = 16;   // batch groups
constexpr int NB  = 16;   // batch rows per group

// ---------------- device scratch ----------------
__device__ float g_xp[3 * MH];               // projected inputs [gate][m][H]
__device__ float g_h [NBG][NB][H_];          // pre-decayed h exchange
__device__ float g_rh[NBG][NB][H_];          // (r * h_dec) exchange
__device__ unsigned int g_ctr[NBG][2];       // per-group barrier counters

// ---------------- f32x2 helpers ----------------
__device__ __forceinline__ unsigned long long pack2(float a, float b) {
    unsigned long long r;
    asm("mov.b64 %0, {%1,%2};" : "=l"(r) : "f"(a), "f"(b));
    return r;
}
__device__ __forceinline__ void fma2(unsigned long long& d, unsigned long long a, unsigned long long b) {
    asm("fma.rn.f32x2 %0, %1, %2, %0;" : "+l"(d) : "l"(a), "l"(b));
}
__device__ __forceinline__ unsigned long long add2(unsigned long long a, unsigned long long b) {
    unsigned long long r;
    asm("add.rn.f32x2 %0, %1, %2;" : "=l"(r) : "l"(a), "l"(b));
    return r;
}
__device__ __forceinline__ float fold2(unsigned long long v) {
    float lo, hi;
    asm("mov.b64 {%0,%1}, %2;" : "=f"(lo), "=f"(hi) : "l"(v));
    return lo + hi;
}
__device__ __forceinline__ void unpack2(unsigned long long v, float& lo, float& hi) {
    asm("mov.b64 {%0,%1}, %2;" : "=f"(lo), "=f"(hi) : "l"(v));
}

__device__ __forceinline__ float sigmoid_(float v) {
    float e = __expf(-v);
    return __fdividef(1.f, 1.f + e);
}
__device__ __forceinline__ float tanh_(float v) {
    float e = __expf(2.f * v);
    return __fdividef(e - 1.f, e + 1.f);
}

// ---------------- inter-CTA barrier primitives ----------------
__device__ __forceinline__ void bar_arrive(unsigned* c) {
    asm volatile("red.release.gpu.global.add.u32 [%0], %1;" :: "l"(c), "r"(1u) : "memory");
}
__device__ __forceinline__ void bar_wait(unsigned* c, unsigned tgt) {
    unsigned v;
    do {
        asm volatile("ld.acquire.gpu.global.u32 %0, [%1];" : "=r"(v) : "l"(c) : "memory");
    } while (v < tgt);
}

// ================= projection GEMM (f32x2 inner loop) =================
// g_xp[g] = x @ W_g + b_g.  x:[131072,128], W:[128,256]. Tile 128M x 64N, BK=32.
// f32x2 pairs span two adjacent m-rows; B values duplicated into both lanes.
__global__ __launch_bounds__(256) void proj_kernel(
    const float* __restrict__ x,
    const float* __restrict__ Wz, const float* __restrict__ Wr, const float* __restrict__ Wh,
    const float* __restrict__ bz, const float* __restrict__ br, const float* __restrict__ bh)
{
    __shared__ float As[32 * 136];   // [k][m], pad 136 (8-float pad keeps 16B align)
    __shared__ float Bs[32 * 64];    // [k][n]

    const int g = blockIdx.z;
    const float* W    = (g == 0) ? Wz : (g == 1) ? Wr : Wh;
    const float* bias = (g == 0) ? bz : (g == 1) ? br : bh;
    float* out = g_xp + (size_t)g * MH;

    const int mtile = blockIdx.x * 128;
    const int ntile = blockIdx.y * 64;
    const int tid = threadIdx.x;
    const int tm = tid >> 4;      // 0..15 -> 8 m-rows (4 pairs) each
    const int tn = tid & 15;      // 0..15 -> 4 n-cols each

    unsigned long long acc[4][4] = {};   // [m-pair][n]

    for (int kc = 0; kc < 128; kc += 32) {
        __syncthreads();
        #pragma unroll
        for (int it = 0; it < 4; ++it) {
            int idx = tid + it * 256;
            int m = idx >> 3, c4 = idx & 7;
            float4 v = *(const float4*)&x[(size_t)(mtile + m) * 128 + kc + c4 * 4];
            As[(c4 * 4 + 0) * 136 + m] = v.x;
            As[(c4 * 4 + 1) * 136 + m] = v.y;
            As[(c4 * 4 + 2) * 136 + m] = v.z;
            As[(c4 * 4 + 3) * 136 + m] = v.w;
        }
        #pragma unroll
        for (int it = 0; it < 2; ++it) {
            int idx = tid + it * 256;
            int kk = idx >> 4, n4 = idx & 15;
            float4 v = *(const float4*)&W[(size_t)(kc + kk) * 256 + ntile + n4 * 4];
            *(float4*)&Bs[kk * 64 + n4 * 4] = v;
        }
        __syncthreads();

        #pragma unroll
        for (int kk = 0; kk < 32; ++kk) {
            // a as 4 packed m-pairs (contiguous rows in As[k][m])
            ulonglong2 ap0 = *(const ulonglong2*)&As[kk * 136 + tm * 8];
            ulonglong2 ap1 = *(const ulonglong2*)&As[kk * 136 + tm * 8 + 4];
            float4 bv = *(const float4*)&Bs[kk * 64 + tn * 4];
            unsigned long long b2[4];
            b2[0] = pack2(bv.x, bv.x);
            b2[1] = pack2(bv.y, bv.y);
            b2[2] = pack2(bv.z, bv.z);
            b2[3] = pack2(bv.w, bv.w);
            unsigned long long a2[4] = {ap0.x, ap0.y, ap1.x, ap1.y};
            #pragma unroll
            for (int p = 0; p < 4; ++p) {
                fma2(acc[p][0], a2[p], b2[0]);
                fma2(acc[p][1], a2[p], b2[1]);
                fma2(acc[p][2], a2[p], b2[2]);
                fma2(acc[p][3], a2[p], b2[3]);
            }
        }
    }

    float4 bb = *(const float4*)&bias[ntile + tn * 4];
    #pragma unroll
    for (int p = 0; p < 4; ++p) {
        float lo[4], hi[4];
        unpack2(acc[p][0], lo[0], hi[0]);
        unpack2(acc[p][1], lo[1], hi[1]);
        unpack2(acc[p][2], lo[2], hi[2]);
        unpack2(acc[p][3], lo[3], hi[3]);
        float4 o0 = make_float4(lo[0] + bb.x, lo[1] + bb.y, lo[2] + bb.z, lo[3] + bb.w);
        float4 o1 = make_float4(hi[0] + bb.x, hi[1] + bb.y, hi[2] + bb.z, hi[3] + bb.w);
        *(float4*)&out[(size_t)(mtile + tm * 8 + 2 * p)     * 256 + ntile + tn * 4] = o0;
        *(float4*)&out[(size_t)(mtile + tm * 8 + 2 * p + 1) * 256 + ntile + tn * 4] = o1;
    }
}

// ================= barrier reset =================
__global__ void reset_kernel() {
    if (threadIdx.x < NBG * 2) ((unsigned*)g_ctr)[threadIdx.x] = 0;
}

// ================= persistent recurrent scan =================
__global__ __launch_bounds__(256, 1) void scan_kernel(
    const float* __restrict__ Uz, const float* __restrict__ Ur, const float* __restrict__ Uh,
    const float* __restrict__ hdecay, float* __restrict__ out)
{
    extern __shared__ float sm[];
    float* asm_s = sm;                                           // [16][256]   16KB
    unsigned long long* red_z = (unsigned long long*)(sm + 4096);  // [8][16][32] u64 32KB
    unsigned long long* red_r = (unsigned long long*)(sm + 12288); // [8][16][32] u64 32KB

    const int tid = threadIdx.x;
    const int w = tid >> 5;          // warp -> k block [32w, 32w+32)
    const int l = tid & 31;          // lane -> local column
    const int grp = blockIdx.x >> 3;
    const int cg  = blockIdx.x & 7;
    const int j = cg * HC + l;
    const int b0g = grp * NB;

    // weights as packed f32x2 over k-pairs
    unsigned long long uz2[16], ur2[16], uh2[16];
    #pragma unroll
    for (int p = 0; p < 16; ++p) {
        int k = w * 32 + 2 * p;
        uz2[p] = pack2(Uz[(size_t)k * H_ + j], Uz[(size_t)(k + 1) * H_ + j]);
        ur2[p] = pack2(Ur[(size_t)k * H_ + j], Ur[(size_t)(k + 1) * H_ + j]);
        uh2[p] = pack2(Uh[(size_t)k * H_ + j], Uh[(size_t)(k + 1) * H_ + j]);
    }

    unsigned* ctrA = &g_ctr[grp][0];
    unsigned* ctrB = &g_ctr[grp][1];

    // h_dec(t=0) = 0
    #pragma unroll
    for (int i = 0; i < 16; ++i) asm_s[tid + i * 256] = 0.f;
    __syncthreads();

    // prefetch x for t=0
    size_t mm0 = (size_t)(b0g + w) * T_;
    size_t mm1 = (size_t)(b0g + w + 8) * T_;
    float xz0 = g_xp[mm0 * 256 + j],          xz1 = g_xp[mm1 * 256 + j];
    float xr0 = g_xp[MH + mm0 * 256 + j],     xr1 = g_xp[MH + mm1 * 256 + j];
    float xh0 = g_xp[2 * MH + mm0 * 256 + j], xh1 = g_xp[2 * MH + mm1 * 256 + j];

    for (int t = 0; t < T_; ++t) {
        const unsigned tgt = (unsigned)(t + 1) * NC;
        const size_t m0 = (size_t)(b0g + w) * T_ + t;
        const size_t m1 = (size_t)(b0g + w + 8) * T_ + t;

        float decn0 = 0.f, decn1 = 0.f;
        if (t + 1 < T_) {
            decn0 = hdecay[m0 + 1];
            decn1 = hdecay[m1 + 1];
        }
        const float hd0 = asm_s[w * 256 + j];
        const float hd1 = asm_s[(w + 8) * 256 + j];

        // ---- merged z+r GEMM (one pass over asm_s) ----
        #pragma unroll 1
        for (int b = 0; b < NB; ++b) {
            unsigned long long az0 = 0, az1 = 0, ar0 = 0, ar1 = 0;
            const float* hrow = &asm_s[b * 256 + w * 32];
            #pragma unroll
            for (int q = 0; q < 8; ++q) {
                ulonglong2 hv = *(const ulonglong2*)(hrow + q * 4);
                fma2(az0, hv.x, uz2[2 * q]);
                fma2(az1, hv.y, uz2[2 * q + 1]);
                fma2(ar0, hv.x, ur2[2 * q]);
                fma2(ar1, hv.y, ur2[2 * q + 1]);
            }
            red_z[(w * 16 + b) * 32 + l] = add2(az0, az1);
            red_r[(w * 16 + b) * 32 + l] = add2(ar0, ar1);
        }
        __syncthreads();

        // ---- r reduce + publish rh ----
        {
            unsigned long long s0 = 0, s1 = 0;
            #pragma unroll
            for (int ww = 0; ww < 8; ++ww) {
                s0 = add2(s0, red_r[(ww * 16 + w) * 32 + l]);
                s1 = add2(s1, red_r[(ww * 16 + w + 8) * 32 + l]);
            }
            float r0 = sigmoid_(fold2(s0) + xr0);
            float r1 = sigmoid_(fold2(s1) + xr1);
            __stcg(&g_rh[grp][w][j],     r0 * hd0);
            __stcg(&g_rh[grp][w + 8][j], r1 * hd1);
        }
        __threadfence();
        __syncthreads();
        if (tid == 0) bar_arrive(ctrA);

        // ---- z reduce (hides barrier A propagation) ----
        float zv0, zv1;
        {
            unsigned long long s0 = 0, s1 = 0;
            #pragma unroll
            for (int ww = 0; ww < 8; ++ww) {
                s0 = add2(s0, red_z[(ww * 16 + w) * 32 + l]);
                s1 = add2(s1, red_z[(ww * 16 + w + 8) * 32 + l]);
            }
            zv0 = sigmoid_(fold2(s0) + xz0);
            zv1 = sigmoid_(fold2(s1) + xz1);
        }
        if (tid == 0) bar_wait(ctrA, tgt);
        __syncthreads();

        // ---- pull full rh rows ----
        #pragma unroll
        for (int it = 0; it < 4; ++it) {
            int idx = tid + it * 256;
            int b = idx >> 6, k4 = idx & 63;
            float4 v = __ldcg((const float4*)&g_rh[grp][b][k4 * 4]);
            *(float4*)&asm_s[b * 256 + k4 * 4] = v;
        }
        __syncthreads();

        // ---- h GEMM ----
        #pragma unroll 1
        for (int b = 0; b < NB; ++b) {
            unsigned long long ah0 = 0, ah1 = 0;
            const float* hrow = &asm_s[b * 256 + w * 32];
            #pragma unroll
            for (int q = 0; q < 8; ++q) {
                ulonglong2 hv = *(const ulonglong2*)(hrow + q * 4);
                fma2(ah0, hv.x, uh2[2 * q]);
                fma2(ah1, hv.y, uh2[2 * q + 1]);
            }
            red_z[(w * 16 + b) * 32 + l] = add2(ah0, ah1);
        }
        __syncthreads();

        // ---- h reduce, combine, publish pre-decayed h ----
        float h0, h1;
        {
            unsigned long long s0 = 0, s1 = 0;
            #pragma unroll
            for (int ww = 0; ww < 8; ++ww) {
                s0 = add2(s0, red_z[(ww * 16 + w) * 32 + l]);
                s1 = add2(s1, red_z[(ww * 16 + w + 8) * 32 + l]);
            }
            float hp0 = tanh_(fold2(s0) + xh0);
            float hp1 = tanh_(fold2(s1) + xh1);
            h0 = (1.f - zv0) * hd0 + zv0 * hp0;
            h1 = (1.f - zv1) * hd1 + zv1 * hp1;
            __stcg(&g_h[grp][w][j],     h0 * decn0);
            __stcg(&g_h[grp][w + 8][j], h1 * decn1);
        }
        __threadfence();        // drain only the 2 g_h stores
        __syncthreads();
        if (tid == 0) bar_arrive(ctrB);

        // off-critical-path work while barrier B propagates:
        __stcg(&out[m0 * 256 + j], h0);
        __stcg(&out[m1 * 256 + j], h1);
        if (t + 1 < T_) {       // prefetch next step's x (DRAM latency covered)
            xz0 = g_xp[(m0 + 1) * 256 + j];          xz1 = g_xp[(m1 + 1) * 256 + j];
            xr0 = g_xp[MH + (m0 + 1) * 256 + j];     xr1 = g_xp[MH + (m1 + 1) * 256 + j];
            xh0 = g_xp[2 * MH + (m0 + 1) * 256 + j]; xh1 = g_xp[2 * MH + (m1 + 1) * 256 + j];
        }
        if (tid == 0) bar_wait(ctrB, tgt);
        __syncthreads();

        // ---- assemble next h_dec (already decayed) ----
        if (t + 1 < T_) {
            #pragma unroll
            for (int it = 0; it < 4; ++it) {
                int idx = tid + it * 256;
                int b = idx >> 6, k4 = idx & 63;
                float4 v = __ldcg((const float4*)&g_h[grp][b][k4 * 4]);
                *(float4*)&asm_s[b * 256 + k4 * 4] = v;
            }
            __syncthreads();
        }
    }
}

// ================= launch =================
extern "C" void kernel_launch(void* const* d_in, const int* /*in_sizes*/, int /*n_in*/,
                              void* d_out, int /*out_size*/)
{
    const float* x      = (const float*)d_in[0];
    const float* hdecay = (const float*)d_in[1];
    const float* Wr = (const float*)d_in[2];
    const float* Wz = (const float*)d_in[3];
    const float* Wh = (const float*)d_in[4];
    const float* Ur = (const float*)d_in[5];
    const float* Uz = (const float*)d_in[6];
    const float* Uh = (const float*)d_in[7];
    const float* br = (const float*)d_in[8];
    const float* bz = (const float*)d_in[9];
    const float* bh = (const float*)d_in[10];
    float* out = (float*)d_out;

    constexpr int SMEM_SCAN = 20480 * 4;   // 80KB dynamic
    cudaFuncSetAttribute(scan_kernel, cudaFuncAttributeMaxDynamicSharedMemorySize, SMEM_SCAN);

    proj_kernel<<<dim3(MTOT / 128, H_ / 64, 3), 256>>>(x, Wz, Wr, Wh, bz, br, bh);
    reset_kernel<<<1, 32>>>();
    scan_kernel<<<NBG * NC, 256, SMEM_SCAN>>>(Uz, Ur, Uh, hdecay, out);
}